// round 1
// baseline (speedup 1.0000x reference)
#include <cuda_runtime.h>
#include <math.h>

// Fixed problem shapes
#define CL1 32896   // total ragged tokens = 256*257/2
#define CB  256     // batches
#define CD  256     // hidden
#define CH  4       // heads
#define CHD 64      // head dim
#define TB  16      // tokens per GEMM block
#define KPAD 65     // padded K/V smem row stride (bank-conflict-free)

// Scratch (device globals; no allocation allowed)
__device__ int   g_starts[CB];
__device__ int   g_pos[CL1];
__device__ float g_qcat[CL1 * CD];
__device__ float g_Q[CL1 * CD];
__device__ float g_K[CL1 * CD];
__device__ float g_V[CL1 * CD];
__device__ float g_ctx[CL1 * CD];
__device__ float g_h[CL1 * CD];

// ---------------------------------------------------------------------------
// Kernel 0: ragged index construction (starts + local positions)
// ---------------------------------------------------------------------------
__global__ void k_index(const int* __restrict__ sl) {
    __shared__ int st[CB];
    int tid = threadIdx.x;
    if (tid == 0) {
        int a = 0;
        for (int b = 0; b < CB; b++) { st[b] = a; a += sl[b]; }
    }
    __syncthreads();
    int s = st[tid];
    int len = sl[tid];
    g_starts[tid] = s;
    for (int i = 0; i < len; i++) g_pos[s + i] = i;
}

// ---------------------------------------------------------------------------
// Kernel 1: fused (emb + pos_table[p+SHIFT]) @ W + b   ([L1,256]x[256,256])
// 16 tokens per block, 256 threads, thread = one output column.
// ---------------------------------------------------------------------------
template <int SHIFT, bool SAVEQ>
__global__ __launch_bounds__(256) void k_proj(
    const float* __restrict__ emb, const float* __restrict__ pt,
    const float* __restrict__ W, const float* __restrict__ bias,
    float* __restrict__ out) {
    __shared__ float xs[TB][CD];
    int t0 = blockIdx.x * TB, tid = threadIdx.x;
#pragma unroll
    for (int r = 0; r < TB; r++) {
        int t = t0 + r;
        float v = emb[t * CD + tid] + pt[(g_pos[t] + SHIFT) * CD + tid];
        xs[r][tid] = v;
        if (SAVEQ) g_qcat[t * CD + tid] = v;
    }
    __syncthreads();
    float acc[TB];
#pragma unroll
    for (int r = 0; r < TB; r++) acc[r] = 0.f;
    const float4* xs4 = (const float4*)&xs[0][0];
#pragma unroll 2
    for (int k4 = 0; k4 < CD / 4; k4++) {
        float w0 = W[(4 * k4 + 0) * CD + tid];
        float w1 = W[(4 * k4 + 1) * CD + tid];
        float w2 = W[(4 * k4 + 2) * CD + tid];
        float w3 = W[(4 * k4 + 3) * CD + tid];
#pragma unroll
        for (int r = 0; r < TB; r++) {
            float4 xv = xs4[r * (CD / 4) + k4];
            acc[r] = fmaf(xv.x, w0, acc[r]);
            acc[r] = fmaf(xv.y, w1, acc[r]);
            acc[r] = fmaf(xv.z, w2, acc[r]);
            acc[r] = fmaf(xv.w, w3, acc[r]);
        }
    }
    float bv = bias[tid];
#pragma unroll
    for (int r = 0; r < TB; r++) out[(t0 + r) * CD + tid] = acc[r] + bv;
}

// ---------------------------------------------------------------------------
// Kernel 2: zero-attention per (batch, head). Warp = one query row.
// Softmax includes a zero-slot key (score 0, value 0).
// ---------------------------------------------------------------------------
__global__ __launch_bounds__(256) void k_attn(const int* __restrict__ sl) {
    extern __shared__ float sm[];
    float* Kh    = sm;                    // 256*KPAD
    float* Vh    = Kh + 256 * KPAD;       // 256*KPAD
    float* probs = Vh + 256 * KPAD;       // 8*256 (per warp)
    float* qb    = probs + 8 * 256;       // 8*64  (per warp)
    int b = blockIdx.x, h = blockIdx.y;
    int L = sl[b], start = g_starts[b];
    int tid = threadIdx.x;

    for (int idx = tid; idx < L * CHD; idx += 256) {
        int r = idx >> 6, c = idx & 63;
        Kh[r * KPAD + c] = g_K[(start + r) * CD + h * CHD + c];
        Vh[r * KPAD + c] = g_V[(start + r) * CD + h * CHD + c];
    }
    __syncthreads();

    int w = tid >> 5, lane = tid & 31;
    for (int q = w; q < L; q += 8) {
        qb[w * CHD + lane]      = g_Q[(start + q) * CD + h * CHD + lane];
        qb[w * CHD + 32 + lane] = g_Q[(start + q) * CD + h * CHD + 32 + lane];
        __syncwarp();

        // scores: lane owns keys j = lane + 32*jj
        const float* kp[8];
#pragma unroll
        for (int jj = 0; jj < 8; jj++) {
            int j = lane + 32 * jj;
            kp[jj] = &Kh[(j < L ? j : 0) * KPAD];
        }
        float s[8];
#pragma unroll
        for (int jj = 0; jj < 8; jj++) s[jj] = 0.f;
        for (int d = 0; d < CHD; d++) {
            float qd = qb[w * CHD + d];
#pragma unroll
            for (int jj = 0; jj < 8; jj++) s[jj] = fmaf(qd, kp[jj][d], s[jj]);
        }
        float m = 0.f;  // zero-slot score is 0
#pragma unroll
        for (int jj = 0; jj < 8; jj++) {
            int j = lane + 32 * jj;
            s[jj] = (j < L) ? s[jj] * 0.125f : -1e30f;
            m = fmaxf(m, s[jj]);
        }
#pragma unroll
        for (int o = 16; o; o >>= 1) m = fmaxf(m, __shfl_xor_sync(0xffffffffu, m, o));
        float dsum = (lane == 0) ? __expf(0.f - m) : 0.f;  // zero-slot term once
#pragma unroll
        for (int jj = 0; jj < 8; jj++) {
            int j = lane + 32 * jj;
            if (j < L) {
                float p = __expf(s[jj] - m);
                probs[w * 256 + j] = p;
                dsum += p;
            }
        }
#pragma unroll
        for (int o = 16; o; o >>= 1) dsum += __shfl_xor_sync(0xffffffffu, dsum, o);
        float inv = 1.f / dsum;
        __syncwarp();

        // ctx: lane owns output dims lane and lane+32
        float c0 = 0.f, c1 = 0.f;
        for (int j = 0; j < L; j++) {
            float p = probs[w * 256 + j];
            c0 = fmaf(p, Vh[j * KPAD + lane], c0);
            c1 = fmaf(p, Vh[j * KPAD + 32 + lane], c1);
        }
        g_ctx[(start + q) * CD + h * CHD + lane]      = c0 * inv;
        g_ctx[(start + q) * CD + h * CHD + 32 + lane] = c1 * inv;
        __syncwarp();
    }
}

// ---------------------------------------------------------------------------
// Kernel 3: h = LayerNorm(ctx @ wo + bo + q_cat)
// ---------------------------------------------------------------------------
__global__ __launch_bounds__(256) void k_selfout(
    const float* __restrict__ wo, const float* __restrict__ bo,
    const float* __restrict__ lng, const float* __restrict__ lnb) {
    __shared__ float xs[TB][CD];
    __shared__ float hb[TB][CD];
    __shared__ float mu[TB], rs[TB];
    int t0 = blockIdx.x * TB, tid = threadIdx.x;
#pragma unroll
    for (int r = 0; r < TB; r++) xs[r][tid] = g_ctx[(t0 + r) * CD + tid];
    __syncthreads();
    float acc[TB];
#pragma unroll
    for (int r = 0; r < TB; r++) acc[r] = 0.f;
    const float4* xs4 = (const float4*)&xs[0][0];
#pragma unroll 2
    for (int k4 = 0; k4 < CD / 4; k4++) {
        float w0 = wo[(4 * k4 + 0) * CD + tid];
        float w1 = wo[(4 * k4 + 1) * CD + tid];
        float w2 = wo[(4 * k4 + 2) * CD + tid];
        float w3 = wo[(4 * k4 + 3) * CD + tid];
#pragma unroll
        for (int r = 0; r < TB; r++) {
            float4 xv = xs4[r * (CD / 4) + k4];
            acc[r] = fmaf(xv.x, w0, acc[r]);
            acc[r] = fmaf(xv.y, w1, acc[r]);
            acc[r] = fmaf(xv.z, w2, acc[r]);
            acc[r] = fmaf(xv.w, w3, acc[r]);
        }
    }
    float bv = bo[tid];
#pragma unroll
    for (int r = 0; r < TB; r++) {
        acc[r] += bv + g_qcat[(t0 + r) * CD + tid];
        hb[r][tid] = acc[r];
    }
    __syncthreads();
    int w = tid >> 5, lane = tid & 31;
#pragma unroll
    for (int rr = 0; rr < TB / 8; rr++) {
        int r = w + 8 * rr;
        float s1 = 0.f, s2 = 0.f;
        for (int c = lane; c < CD; c += 32) {
            float v = hb[r][c];
            s1 += v; s2 += v * v;
        }
#pragma unroll
        for (int o = 16; o; o >>= 1) {
            s1 += __shfl_xor_sync(0xffffffffu, s1, o);
            s2 += __shfl_xor_sync(0xffffffffu, s2, o);
        }
        if (lane == 0) {
            float mm = s1 * (1.f / CD);
            mu[r] = mm;
            rs[r] = rsqrtf(s2 * (1.f / CD) - mm * mm + 1e-12f);
        }
    }
    __syncthreads();
    float gg = lng[tid], bb = lnb[tid];
#pragma unroll
    for (int r = 0; r < TB; r++)
        g_h[(t0 + r) * CD + tid] = (acc[r] - mu[r]) * rs[r] * gg + bb;
}

// ---------------------------------------------------------------------------
// Kernel 4: out = gelu(concat(h, q_cat) @ wm + bm)   (exact erf gelu)
// ---------------------------------------------------------------------------
__global__ __launch_bounds__(256) void k_merge(
    const float* __restrict__ wm, const float* __restrict__ bm,
    float* __restrict__ out) {
    __shared__ float xs[TB][2 * CD];
    int t0 = blockIdx.x * TB, tid = threadIdx.x;
#pragma unroll
    for (int r = 0; r < TB; r++) {
        xs[r][tid]      = g_h[(t0 + r) * CD + tid];
        xs[r][CD + tid] = g_qcat[(t0 + r) * CD + tid];
    }
    __syncthreads();
    float acc[TB];
#pragma unroll
    for (int r = 0; r < TB; r++) acc[r] = 0.f;
    const float4* xs4 = (const float4*)&xs[0][0];
#pragma unroll 2
    for (int k4 = 0; k4 < (2 * CD) / 4; k4++) {
        float w0 = wm[(4 * k4 + 0) * CD + tid];
        float w1 = wm[(4 * k4 + 1) * CD + tid];
        float w2 = wm[(4 * k4 + 2) * CD + tid];
        float w3 = wm[(4 * k4 + 3) * CD + tid];
#pragma unroll
        for (int r = 0; r < TB; r++) {
            float4 xv = xs4[r * (2 * CD / 4) + k4];
            acc[r] = fmaf(xv.x, w0, acc[r]);
            acc[r] = fmaf(xv.y, w1, acc[r]);
            acc[r] = fmaf(xv.z, w2, acc[r]);
            acc[r] = fmaf(xv.w, w3, acc[r]);
        }
    }
    float bv = bm[tid];
#pragma unroll
    for (int r = 0; r < TB; r++) {
        float x = acc[r] + bv;
        out[(t0 + r) * CD + tid] = 0.5f * x * (1.f + erff(x * 0.70710678118654752440f));
    }
}

// ---------------------------------------------------------------------------
extern "C" void kernel_launch(void* const* d_in, const int* in_sizes, int n_in,
                              void* d_out, int out_size) {
    const float* qe  = (const float*)d_in[0];
    const float* ke  = (const float*)d_in[1];
    const float* ve  = (const float*)d_in[2];
    const float* pt  = (const float*)d_in[3];
    const float* wq  = (const float*)d_in[4];
    const float* bq  = (const float*)d_in[5];
    const float* wk  = (const float*)d_in[6];
    const float* bk  = (const float*)d_in[7];
    const float* wv  = (const float*)d_in[8];
    const float* bv  = (const float*)d_in[9];
    const float* wo  = (const float*)d_in[10];
    const float* bo  = (const float*)d_in[11];
    const float* lng = (const float*)d_in[12];
    const float* lnb = (const float*)d_in[13];
    const float* wm  = (const float*)d_in[14];
    const float* bm  = (const float*)d_in[15];
    const int*   sl  = (const int*)d_in[16];
    float* out = (float*)d_out;

    float *gQ, *gK, *gV;
    cudaGetSymbolAddress((void**)&gQ, g_Q);
    cudaGetSymbolAddress((void**)&gK, g_K);
    cudaGetSymbolAddress((void**)&gV, g_V);

    constexpr int GB = CL1 / TB;  // 2056 blocks, exact

    k_index<<<1, CB>>>(sl);
    k_proj<1, true ><<<GB, 256>>>(qe, pt, wq, bq, gQ);
    k_proj<0, false><<<GB, 256>>>(ke, pt, wk, bk, gK);
    k_proj<0, false><<<GB, 256>>>(ve, pt, wv, bv, gV);

    constexpr size_t ASM = (size_t)(2 * 256 * KPAD + 8 * 256 + 8 * 64) * sizeof(float);
    cudaFuncSetAttribute(k_attn, cudaFuncAttributeMaxDynamicSharedMemorySize, (int)ASM);
    k_attn<<<dim3(CB, CH), 256, ASM>>>(sl);

    k_selfout<<<GB, 256>>>(wo, bo, lng, lnb);
    k_merge<<<GB, 256>>>(wm, bm, out);
}

// round 2
// speedup vs baseline: 2.7030x; 2.7030x over previous
#include <cuda_runtime.h>
#include <math.h>

// Fixed problem shapes
#define CL1 32896   // total ragged tokens = 256*257/2
#define CB  256     // batches
#define CD  256     // hidden
#define CH  4       // heads
#define CHD 64      // head dim
#define BM  32      // tokens per GEMM block
#define XST 36      // xsT smem stride (float4-aligned, low-conflict transpose writes)

// Scratch (device globals; no allocation allowed)
__device__ int   g_starts[CB];
__device__ int   g_pos[CL1];
__device__ float g_qcat[CL1 * CD];
__device__ float g_Q[CL1 * CD];
__device__ float g_K[CL1 * CD];
__device__ float g_V[CL1 * CD];
__device__ float g_ctx[CL1 * CD];
__device__ float g_h[CL1 * CD];

// ---------------------------------------------------------------------------
// Kernel 0: ragged index construction (starts + local positions)
// ---------------------------------------------------------------------------
__global__ void k_index(const int* __restrict__ sl) {
    __shared__ int st[CB];
    int tid = threadIdx.x;
    if (tid == 0) {
        int a = 0;
        for (int b = 0; b < CB; b++) { st[b] = a; a += sl[b]; }
    }
    __syncthreads();
    int s = st[tid];
    int len = sl[tid];
    g_starts[tid] = s;
    for (int i = 0; i < len; i++) g_pos[s + i] = i;
}

// ---------------------------------------------------------------------------
// Shared GEMM mainloop: acc[8][4] += xsT^T @ W  over K=256.
// Thread tile: 8 tokens (mg) x 4 cols (cg). a = broadcast LDS.128 x2,
// b = 1 coalesced LDG.128. 3 mem instr per 32 FMA.
// ---------------------------------------------------------------------------
__device__ __forceinline__ void gemm_k256(
    const float* __restrict__ xsT, const float* __restrict__ W,
    int cg, int mg, float acc[8][4]) {
    const float* Wp = W + cg * 4;
    const float* Ap = xsT + mg * 8;
#pragma unroll 4
    for (int k = 0; k < 256; k++) {
        float4 b = *(const float4*)(Wp + k * CD);
        float4 a0 = *(const float4*)(Ap + k * XST);
        float4 a1 = *(const float4*)(Ap + k * XST + 4);
        float a[8] = {a0.x, a0.y, a0.z, a0.w, a1.x, a1.y, a1.z, a1.w};
#pragma unroll
        for (int i = 0; i < 8; i++) {
            acc[i][0] = fmaf(a[i], b.x, acc[i][0]);
            acc[i][1] = fmaf(a[i], b.y, acc[i][1]);
            acc[i][2] = fmaf(a[i], b.z, acc[i][2]);
            acc[i][3] = fmaf(a[i], b.w, acc[i][3]);
        }
    }
}

// ---------------------------------------------------------------------------
// Kernel 1: fused (emb + pos_table[p+SHIFT]) @ W + b
// ---------------------------------------------------------------------------
template <int SHIFT, bool SAVEQ>
__global__ __launch_bounds__(256, 1) void k_proj(
    const float* __restrict__ emb, const float* __restrict__ pt,
    const float* __restrict__ W, const float* __restrict__ bias,
    float* __restrict__ out) {
    __shared__ float xsT[CD * XST];
    __shared__ int spos[BM];
    int t0 = blockIdx.x * BM, tid = threadIdx.x;
    if (tid < BM) spos[tid] = g_pos[t0 + tid];
    __syncthreads();
    int c = tid;
#pragma unroll
    for (int t = 0; t < BM; t += 4) {
        float4 v;
        v.x = emb[(t0 + t + 0) * CD + c] + pt[(spos[t + 0] + SHIFT) * CD + c];
        v.y = emb[(t0 + t + 1) * CD + c] + pt[(spos[t + 1] + SHIFT) * CD + c];
        v.z = emb[(t0 + t + 2) * CD + c] + pt[(spos[t + 2] + SHIFT) * CD + c];
        v.w = emb[(t0 + t + 3) * CD + c] + pt[(spos[t + 3] + SHIFT) * CD + c];
        if (SAVEQ) {
            g_qcat[(t0 + t + 0) * CD + c] = v.x;
            g_qcat[(t0 + t + 1) * CD + c] = v.y;
            g_qcat[(t0 + t + 2) * CD + c] = v.z;
            g_qcat[(t0 + t + 3) * CD + c] = v.w;
        }
        *(float4*)&xsT[c * XST + t] = v;
    }
    __syncthreads();
    int cg = tid & 63, mg = tid >> 6;
    float acc[8][4];
#pragma unroll
    for (int i = 0; i < 8; i++)
#pragma unroll
        for (int j = 0; j < 4; j++) acc[i][j] = 0.f;
    gemm_k256(xsT, W, cg, mg, acc);
    float4 b4 = *(const float4*)(bias + cg * 4);
#pragma unroll
    for (int i = 0; i < 8; i++) {
        float4 o = make_float4(acc[i][0] + b4.x, acc[i][1] + b4.y,
                               acc[i][2] + b4.z, acc[i][3] + b4.w);
        *(float4*)&out[(t0 + mg * 8 + i) * CD + cg * 4] = o;
    }
}

// ---------------------------------------------------------------------------
// Kernel 2: zero-attention per (batch, head). Warp = 4 query rows per pass.
// K/V in smem as XOR-swizzled float4 chunks: chunk(j,d4) = j*16 + (d4^(j&7))
// -> conflict-free LDS.128 both for per-key (scores) and per-dim (ctx) access.
// ---------------------------------------------------------------------------
__global__ __launch_bounds__(256, 1) void k_attn(const int* __restrict__ sl) {
    extern __shared__ float sm[];
    float4* Ks   = (float4*)sm;               // 256*16 chunks
    float4* Vs   = Ks + 256 * 16;             // 256*16 chunks
    float*  prob = (float*)(Vs + 256 * 16);   // 8 warps * 4 * 256
    float*  qb   = prob + 8 * 4 * 256;        // 8 warps * 4 * 64

    int b = blockIdx.x, h = blockIdx.y;
    int L = sl[b], start = g_starts[b];
    int tid = threadIdx.x;
    int hoff = h * CHD;

    for (int qd = tid; qd < L * 16; qd += 256) {
        int j = qd >> 4, d4 = qd & 15;
        int sw = (j << 4) | (d4 ^ (j & 7));
        Ks[sw] = *(const float4*)&g_K[(start + j) * CD + hoff + (d4 << 2)];
        Vs[sw] = *(const float4*)&g_V[(start + j) * CD + hoff + (d4 << 2)];
    }
    __syncthreads();

    int w = tid >> 5, lane = tid & 31;
    float* pw = prob + w * 1024;
    float* qw = qb + w * 256;
    int lsw = lane & 7;

    for (int q0 = w * 4; q0 < L; q0 += 32) {
        int nq = min(4, L - q0);
        // stage 4 query rows
#pragma unroll
        for (int qi = 0; qi < 4; qi++) {
            if (qi < nq) {
                const float* qp = &g_Q[(start + q0 + qi) * CD + hoff];
                qw[qi * 64 + lane] = qp[lane];
                qw[qi * 64 + 32 + lane] = qp[32 + lane];
            }
        }
        __syncwarp();

        // scores: lane owns keys j = lane + 32*jj
        int jrow[8];
#pragma unroll
        for (int jj = 0; jj < 8; jj++) {
            int j = lane + 32 * jj;
            jrow[jj] = (j < L ? j : 0) << 4;
        }
        float s[4][8];
#pragma unroll
        for (int qi = 0; qi < 4; qi++)
#pragma unroll
            for (int jj = 0; jj < 8; jj++) s[qi][jj] = 0.f;
#pragma unroll 4
        for (int d4 = 0; d4 < 16; d4++) {
            float4 kf[8];
            int swd = d4 ^ lsw;
#pragma unroll
            for (int jj = 0; jj < 8; jj++) kf[jj] = Ks[jrow[jj] + swd];
#pragma unroll
            for (int qi = 0; qi < 4; qi++) {
                float4 qv = *(float4*)&qw[qi * 64 + (d4 << 2)];
#pragma unroll
                for (int jj = 0; jj < 8; jj++) {
                    s[qi][jj] = fmaf(qv.x, kf[jj].x, s[qi][jj]);
                    s[qi][jj] = fmaf(qv.y, kf[jj].y, s[qi][jj]);
                    s[qi][jj] = fmaf(qv.z, kf[jj].z, s[qi][jj]);
                    s[qi][jj] = fmaf(qv.w, kf[jj].w, s[qi][jj]);
                }
            }
        }

        // softmax per query (zero-slot: extra key with score 0, value 0)
        float inv[4];
#pragma unroll
        for (int qi = 0; qi < 4; qi++) {
            if (qi >= nq) continue;
            float m = 0.f;
#pragma unroll
            for (int jj = 0; jj < 8; jj++) {
                int j = lane + 32 * jj;
                s[qi][jj] = (j < L) ? s[qi][jj] * 0.125f : -1e30f;
                m = fmaxf(m, s[qi][jj]);
            }
#pragma unroll
            for (int o = 16; o; o >>= 1) m = fmaxf(m, __shfl_xor_sync(0xffffffffu, m, o));
            float ds = (lane == 0) ? __expf(0.f - m) : 0.f;
#pragma unroll
            for (int jj = 0; jj < 8; jj++) {
                int j = lane + 32 * jj;
                if (j < L) {
                    float p = __expf(s[qi][jj] - m);
                    pw[qi * 256 + j] = p;
                    ds += p;
                }
            }
#pragma unroll
            for (int o = 16; o; o >>= 1) ds += __shfl_xor_sync(0xffffffffu, ds, o);
            inv[qi] = 1.f / ds;
        }
        __syncwarp();

        // ctx: lane owns dim chunk d4c (4 dims) and j-parity
        int d4c = lane & 15, par = lane >> 4;
        float4 cacc[4];
#pragma unroll
        for (int qi = 0; qi < 4; qi++) cacc[qi] = make_float4(0.f, 0.f, 0.f, 0.f);
        for (int j = par; j < L; j += 2) {
            float4 vv = Vs[(j << 4) + (d4c ^ (j & 7))];
#pragma unroll
            for (int qi = 0; qi < 4; qi++) {
                float p = pw[qi * 256 + j];
                cacc[qi].x = fmaf(p, vv.x, cacc[qi].x);
                cacc[qi].y = fmaf(p, vv.y, cacc[qi].y);
                cacc[qi].z = fmaf(p, vv.z, cacc[qi].z);
                cacc[qi].w = fmaf(p, vv.w, cacc[qi].w);
            }
        }
#pragma unroll
        for (int qi = 0; qi < 4; qi++) {
            cacc[qi].x += __shfl_xor_sync(0xffffffffu, cacc[qi].x, 16);
            cacc[qi].y += __shfl_xor_sync(0xffffffffu, cacc[qi].y, 16);
            cacc[qi].z += __shfl_xor_sync(0xffffffffu, cacc[qi].z, 16);
            cacc[qi].w += __shfl_xor_sync(0xffffffffu, cacc[qi].w, 16);
            if (qi < nq && par == 0) {
                float4 o = make_float4(cacc[qi].x * inv[qi], cacc[qi].y * inv[qi],
                                       cacc[qi].z * inv[qi], cacc[qi].w * inv[qi]);
                *(float4*)&g_ctx[(start + q0 + qi) * CD + hoff + (d4c << 2)] = o;
            }
        }
        __syncwarp();
    }
}

// ---------------------------------------------------------------------------
// Kernel 3: h = LayerNorm(ctx @ wo + bo + q_cat)
// ---------------------------------------------------------------------------
__global__ __launch_bounds__(256, 1) void k_selfout(
    const float* __restrict__ wo, const float* __restrict__ bo,
    const float* __restrict__ lng, const float* __restrict__ lnb) {
    __shared__ float xsT[CD * XST];       // reused as hb[32][256] after mainloop
    __shared__ float mu[BM], rsg[BM];
    int t0 = blockIdx.x * BM, tid = threadIdx.x;
    int c = tid;
#pragma unroll
    for (int t = 0; t < BM; t += 4) {
        float4 v;
        v.x = g_ctx[(t0 + t + 0) * CD + c];
        v.y = g_ctx[(t0 + t + 1) * CD + c];
        v.z = g_ctx[(t0 + t + 2) * CD + c];
        v.w = g_ctx[(t0 + t + 3) * CD + c];
        *(float4*)&xsT[c * XST + t] = v;
    }
    __syncthreads();
    int cg = tid & 63, mg = tid >> 6;
    float acc[8][4];
#pragma unroll
    for (int i = 0; i < 8; i++)
#pragma unroll
        for (int j = 0; j < 4; j++) acc[i][j] = 0.f;
    gemm_k256(xsT, wo, cg, mg, acc);
    __syncthreads();   // done with xsT, reuse as hb
    float* hb = xsT;
    float4 b4 = *(const float4*)(bo + cg * 4);
#pragma unroll
    for (int i = 0; i < 8; i++) {
        int t = t0 + mg * 8 + i;
        float4 qc = *(const float4*)&g_qcat[t * CD + cg * 4];
        acc[i][0] += b4.x + qc.x;
        acc[i][1] += b4.y + qc.y;
        acc[i][2] += b4.z + qc.z;
        acc[i][3] += b4.w + qc.w;
        *(float4*)&hb[(mg * 8 + i) * CD + cg * 4] =
            make_float4(acc[i][0], acc[i][1], acc[i][2], acc[i][3]);
    }
    __syncthreads();
    int w = tid >> 5, lane = tid & 31;
#pragma unroll
    for (int rr = 0; rr < 4; rr++) {
        int r = w * 4 + rr;
        float s1 = 0.f, s2 = 0.f;
#pragma unroll
        for (int cc = 0; cc < CD; cc += 32) {
            float v = hb[r * CD + cc + lane];
            s1 += v; s2 += v * v;
        }
#pragma unroll
        for (int o = 16; o; o >>= 1) {
            s1 += __shfl_xor_sync(0xffffffffu, s1, o);
            s2 += __shfl_xor_sync(0xffffffffu, s2, o);
        }
        if (lane == 0) {
            float mm = s1 * (1.f / CD);
            mu[r] = mm;
            rsg[r] = rsqrtf(s2 * (1.f / CD) - mm * mm + 1e-12f);
        }
    }
    __syncthreads();
    float4 g4 = *(const float4*)(lng + cg * 4);
    float4 bb4 = *(const float4*)(lnb + cg * 4);
#pragma unroll
    for (int i = 0; i < 8; i++) {
        int r = mg * 8 + i;
        float m = mu[r], rs = rsg[r];
        float4 o = make_float4((acc[i][0] - m) * rs * g4.x + bb4.x,
                               (acc[i][1] - m) * rs * g4.y + bb4.y,
                               (acc[i][2] - m) * rs * g4.z + bb4.z,
                               (acc[i][3] - m) * rs * g4.w + bb4.w);
        *(float4*)&g_h[(t0 + r) * CD + cg * 4] = o;
    }
}

// ---------------------------------------------------------------------------
// Kernel 4: out = gelu(concat(h, q_cat) @ wm + bm), K=512 in two phases
// ---------------------------------------------------------------------------
__global__ __launch_bounds__(256, 1) void k_merge(
    const float* __restrict__ wm, const float* __restrict__ bm,
    float* __restrict__ out) {
    __shared__ float xsT[CD * XST];
    int t0 = blockIdx.x * BM, tid = threadIdx.x;
    int cg = tid & 63, mg = tid >> 6;
    int c = tid;
    float acc[8][4];
#pragma unroll
    for (int i = 0; i < 8; i++)
#pragma unroll
        for (int j = 0; j < 4; j++) acc[i][j] = 0.f;

    // phase A: h part (wm rows 0..255)
#pragma unroll
    for (int t = 0; t < BM; t += 4) {
        float4 v;
        v.x = g_h[(t0 + t + 0) * CD + c];
        v.y = g_h[(t0 + t + 1) * CD + c];
        v.z = g_h[(t0 + t + 2) * CD + c];
        v.w = g_h[(t0 + t + 3) * CD + c];
        *(float4*)&xsT[c * XST + t] = v;
    }
    __syncthreads();
    gemm_k256(xsT, wm, cg, mg, acc);
    __syncthreads();

    // phase B: qcat part (wm rows 256..511)
#pragma unroll
    for (int t = 0; t < BM; t += 4) {
        float4 v;
        v.x = g_qcat[(t0 + t + 0) * CD + c];
        v.y = g_qcat[(t0 + t + 1) * CD + c];
        v.z = g_qcat[(t0 + t + 2) * CD + c];
        v.w = g_qcat[(t0 + t + 3) * CD + c];
        *(float4*)&xsT[c * XST + t] = v;
    }
    __syncthreads();
    gemm_k256(xsT, wm + 256 * CD, cg, mg, acc);

    float4 b4 = *(const float4*)(bm + cg * 4);
#pragma unroll
    for (int i = 0; i < 8; i++) {
        float x0 = acc[i][0] + b4.x, x1 = acc[i][1] + b4.y;
        float x2 = acc[i][2] + b4.z, x3 = acc[i][3] + b4.w;
        const float r2 = 0.70710678118654752440f;
        float4 o = make_float4(0.5f * x0 * (1.f + erff(x0 * r2)),
                               0.5f * x1 * (1.f + erff(x1 * r2)),
                               0.5f * x2 * (1.f + erff(x2 * r2)),
                               0.5f * x3 * (1.f + erff(x3 * r2)));
        *(float4*)&out[(t0 + mg * 8 + i) * CD + cg * 4] = o;
    }
}

// ---------------------------------------------------------------------------
extern "C" void kernel_launch(void* const* d_in, const int* in_sizes, int n_in,
                              void* d_out, int out_size) {
    const float* qe  = (const float*)d_in[0];
    const float* ke  = (const float*)d_in[1];
    const float* ve  = (const float*)d_in[2];
    const float* pt  = (const float*)d_in[3];
    const float* wq  = (const float*)d_in[4];
    const float* bq  = (const float*)d_in[5];
    const float* wk  = (const float*)d_in[6];
    const float* bk  = (const float*)d_in[7];
    const float* wv  = (const float*)d_in[8];
    const float* bv  = (const float*)d_in[9];
    const float* wo  = (const float*)d_in[10];
    const float* bo  = (const float*)d_in[11];
    const float* lng = (const float*)d_in[12];
    const float* lnb = (const float*)d_in[13];
    const float* wm  = (const float*)d_in[14];
    const float* bm  = (const float*)d_in[15];
    const int*   sl  = (const int*)d_in[16];
    float* out = (float*)d_out;

    float *gQ, *gK, *gV;
    cudaGetSymbolAddress((void**)&gQ, g_Q);
    cudaGetSymbolAddress((void**)&gK, g_K);
    cudaGetSymbolAddress((void**)&gV, g_V);

    constexpr int GB = CL1 / BM;  // 1028 blocks, exact

    k_index<<<1, CB>>>(sl);
    k_proj<1, true ><<<GB, 256>>>(qe, pt, wq, bq, gQ);
    k_proj<0, false><<<GB, 256>>>(ke, pt, wk, bk, gK);
    k_proj<0, false><<<GB, 256>>>(ve, pt, wv, bv, gV);

    // attn smem: K(16384) + V(16384) + probs(8192) + qb(2048) floats
    constexpr size_t ASM = (size_t)(16384 + 16384 + 8192 + 2048) * sizeof(float);
    cudaFuncSetAttribute(k_attn, cudaFuncAttributeMaxDynamicSharedMemorySize, (int)ASM);
    k_attn<<<dim3(CB, CH), 256, ASM>>>(sl);

    k_selfout<<<GB, 256>>>(wo, bo, lng, lnb);
    k_merge<<<GB, 256>>>(wm, bm, out);
}